// round 1
// baseline (speedup 1.0000x reference)
#include <cuda_runtime.h>
#include <cstddef>

#define N_STEPS 4096
#define NU 8
#define R 256
#define NX 64
#define NY 8
#define L 32
#define C_CHUNKS (N_STEPS / L)   // 128
#define QTOT (NU * L)            // 256
#define RSUB 2                   // columns per phase-2 CTA slice

// Scratch (device globals: no allocation allowed in kernel_launch)
__device__ float g_KcatT[QTOT * NX];            // [q][i], q=(t*NU+j) with K[L-1-t]
__device__ float g_AL[NX * NX];                 // A^L row-major
__device__ float g_Pfin[C_CHUNKS * NX * R];     // per-chunk particular final states
__device__ float g_Xstart[C_CHUNKS * NX * R];   // per-chunk boundary states

// ---------------------------------------------------------------------------
// Kernel 0: precompute K[s] = A^s B  (s=0..L-1, stored time-flipped, transposed)
//           and A^L via 5 repeated squarings. Single CTA, 256 threads.
// ---------------------------------------------------------------------------
__global__ void k_precompute(const float* __restrict__ A, const float* __restrict__ B) {
    __shared__ float sP[NX * NX];   // holds A during K-chain, then squaring ping
    __shared__ float sQ[NX * NX];   // squaring pong
    __shared__ float sK0[NX * NU];
    __shared__ float sK1[NX * NU];
    const int t = threadIdx.x;      // 256 threads

    for (int idx = t; idx < NX * NX; idx += 256) sP[idx] = A[idx];
    for (int idx = t; idx < NX * NU; idx += 256) sK0[idx] = B[idx];
    __syncthreads();

    // s = 0: K = B, goes to time block tb = L-1
    for (int idx = t; idx < NX * NU; idx += 256) {
        int i = idx / NU, j = idx % NU;
        g_KcatT[((L - 1) * NU + j) * NX + i] = sK0[idx];
    }
    float* kc = sK0;
    float* kn = sK1;
    for (int s = 1; s < L; s++) {
        __syncthreads();
        for (int idx = t; idx < NX * NU; idx += 256) {
            int i = idx / NU, j = idx % NU;
            float acc = 0.f;
            #pragma unroll 8
            for (int m = 0; m < NX; m++) acc += sP[i * NX + m] * kc[m * NU + j];
            kn[idx] = acc;
            g_KcatT[((L - 1 - s) * NU + j) * NX + i] = acc;
        }
        float* tmp = kc; kc = kn; kn = tmp;
    }

    // A^32 = ((((A^2)^2)^2)^2)^2  (5 squarings)
    float* p = sP;
    float* q = sQ;
    for (int m = 0; m < 5; m++) {
        __syncthreads();
        for (int idx = t; idx < NX * NX; idx += 256) {
            int i = idx / NX, j = idx % NX;
            float acc = 0.f;
            #pragma unroll 8
            for (int k = 0; k < NX; k++) acc += p[i * NX + k] * p[k * NX + j];
            q[idx] = acc;
        }
        float* tmp = p; p = q; q = tmp;
    }
    __syncthreads();
    for (int idx = t; idx < NX * NX; idx += 256) g_AL[idx] = p[idx];
}

// ---------------------------------------------------------------------------
// Kernel 1: Pfin[c] = Kcat(64 x 256) @ Uc(256 x 256), Uc contiguous in u.
// Grid (C_CHUNKS, R/64), 256 threads: thread = (ig in 0..3 row-group, r in 0..63)
// ---------------------------------------------------------------------------
__global__ void k_phase1(const float* __restrict__ u) {
    __shared__ __align__(16) float sU[64 * 64];   // [qq][r]
    __shared__ __align__(16) float sKT[64 * 64];  // [qq][i]
    const int c = blockIdx.x;
    const int r0 = blockIdx.y * 64;
    const int t = threadIdx.x;
    const int r = t & 63;
    const int ig = t >> 6;  // 0..3 -> rows ig*16 .. ig*16+15

    float acc[16];
    #pragma unroll
    for (int m = 0; m < 16; m++) acc[m] = 0.f;

    const float* Uc = u + (size_t)c * L * NU * R;

    for (int qb = 0; qb < QTOT / 64; qb++) {
        __syncthreads();
        #pragma unroll
        for (int m = 0; m < 16; m++) {
            int qq = m * 4 + ig;
            sU[qq * 64 + r] = Uc[(size_t)(qb * 64 + qq) * R + r0 + r];
        }
        for (int idx = t; idx < 4096; idx += 256)
            sKT[idx] = g_KcatT[qb * 64 * 64 + idx];
        __syncthreads();

        #pragma unroll 8
        for (int qq = 0; qq < 64; qq++) {
            float uval = sU[qq * 64 + r];
            const float4* k4 = (const float4*)(sKT + qq * 64 + ig * 16);
            #pragma unroll
            for (int m4 = 0; m4 < 4; m4++) {
                float4 kk = k4[m4];
                acc[m4 * 4 + 0] += kk.x * uval;
                acc[m4 * 4 + 1] += kk.y * uval;
                acc[m4 * 4 + 2] += kk.z * uval;
                acc[m4 * 4 + 3] += kk.w * uval;
            }
        }
    }
    #pragma unroll
    for (int m = 0; m < 16; m++) {
        int i = ig * 16 + m;
        g_Pfin[((size_t)c * NX + i) * R + r0 + r] = acc[m];
    }
}

// ---------------------------------------------------------------------------
// Kernel 2: boundary scan. Xstart[0] = x0; Xstart[c+1] = A^L Xstart[c] + Pfin[c].
// Grid R/RSUB CTAs, block NX*RSUB. thread = (i = t/RSUB, r = t%RSUB).
// ---------------------------------------------------------------------------
__global__ void k_phase2(const float* __restrict__ x0) {
    __shared__ __align__(16) float sAL[NX * NX];
    __shared__ float sx[NX * RSUB];
    const int t = threadIdx.x;                // NX*RSUB = 128
    const int r = t & (RSUB - 1);
    const int i = t / RSUB;
    const int rg = blockIdx.x * RSUB + r;

    for (int idx = t; idx < NX * NX; idx += NX * RSUB) sAL[idx] = g_AL[idx];
    float xi = x0[i * R + rg];
    sx[i * RSUB + r] = xi;
    __syncthreads();

    float pf = g_Pfin[(size_t)i * R + rg];
    for (int c = 0; c < C_CHUNKS; c++) {
        g_Xstart[((size_t)c * NX + i) * R + rg] = xi;
        float pf_next = (c + 1 < C_CHUNKS)
            ? g_Pfin[((size_t)(c + 1) * NX + i) * R + rg] : 0.f;
        float acc = 0.f;
        const float4* a4 = (const float4*)(sAL + i * NX);
        #pragma unroll
        for (int jb = 0; jb < NX / 4; jb++) {
            float4 a = a4[jb];
            acc += a.x * sx[(jb * 4 + 0) * RSUB + r];
            acc += a.y * sx[(jb * 4 + 1) * RSUB + r];
            acc += a.z * sx[(jb * 4 + 2) * RSUB + r];
            acc += a.w * sx[(jb * 4 + 3) * RSUB + r];
        }
        acc += pf;
        __syncthreads();
        xi = acc;
        sx[i * RSUB + r] = xi;
        pf = pf_next;
        __syncthreads();
    }
}

// ---------------------------------------------------------------------------
// Kernel 3: per-chunk sequential simulation, writes Y and X for every step.
// Grid (C_CHUNKS, R/32), single warp per CTA; thread owns one column,
// full state in registers, matrices broadcast from smem via LDS.128.
// ---------------------------------------------------------------------------
__global__ void __launch_bounds__(32) k_phase3(
    const float* __restrict__ u, const float* __restrict__ A,
    const float* __restrict__ B, const float* __restrict__ Cy,
    const float* __restrict__ D,
    float* __restrict__ outY, float* __restrict__ outX)
{
    __shared__ __align__(16) float sA[NX * NX];
    __shared__ __align__(16) float sB[NX * NU];
    __shared__ __align__(16) float sC[NY * NX];
    __shared__ __align__(16) float sD[NY * NU];
    const int c = blockIdx.x;
    const int t = threadIdx.x;
    const int r = blockIdx.y * 32 + t;

    for (int idx = t; idx < NX * NX / 4; idx += 32) ((float4*)sA)[idx] = ((const float4*)A)[idx];
    for (int idx = t; idx < NX * NU / 4; idx += 32) ((float4*)sB)[idx] = ((const float4*)B)[idx];
    for (int idx = t; idx < NY * NX / 4; idx += 32) ((float4*)sC)[idx] = ((const float4*)Cy)[idx];
    for (int idx = t; idx < NY * NU / 4; idx += 32) ((float4*)sD)[idx] = ((const float4*)D)[idx];

    float x[NX];
    #pragma unroll
    for (int i = 0; i < NX; i++) x[i] = g_Xstart[((size_t)c * NX + i) * R + r];
    __syncthreads();

    const float* up = u    + (size_t)c * L * NU * R + r;
    float*       yp = outY + (size_t)c * L * NY * R + r;
    float*       xp = outX + (size_t)c * L * NX * R + r;

    for (int step = 0; step < L; step++) {
        float uu[NU];
        #pragma unroll
        for (int j = 0; j < NU; j++) uu[j] = up[(size_t)j * R];

        // store X[k] (pre-update state)
        #pragma unroll
        for (int i = 0; i < NX; i++) xp[(size_t)i * R] = x[i];

        // Y[k] = C x + D u
        #pragma unroll
        for (int o = 0; o < NY; o++) {
            float acc = 0.f;
            const float4* c4 = (const float4*)(sC + o * NX);
            #pragma unroll
            for (int jb = 0; jb < NX / 4; jb++) {
                float4 a = c4[jb];
                acc += a.x * x[jb * 4 + 0] + a.y * x[jb * 4 + 1]
                     + a.z * x[jb * 4 + 2] + a.w * x[jb * 4 + 3];
            }
            const float4* d4 = (const float4*)(sD + o * NU);
            float4 d0 = d4[0], d1 = d4[1];
            acc += d0.x * uu[0] + d0.y * uu[1] + d0.z * uu[2] + d0.w * uu[3];
            acc += d1.x * uu[4] + d1.y * uu[5] + d1.z * uu[6] + d1.w * uu[7];
            yp[(size_t)o * R] = acc;
        }

        // x <- A x + B u
        float acc[NX];
        #pragma unroll
        for (int i = 0; i < NX; i++) {
            const float4* b4 = (const float4*)(sB + i * NU);
            float4 b0 = b4[0], b1 = b4[1];
            acc[i] = b0.x * uu[0] + b0.y * uu[1] + b0.z * uu[2] + b0.w * uu[3]
                   + b1.x * uu[4] + b1.y * uu[5] + b1.z * uu[6] + b1.w * uu[7];
        }
        #pragma unroll
        for (int jb = 0; jb < NX / 4; jb++) {
            #pragma unroll
            for (int i = 0; i < NX; i++) {
                float4 a = ((const float4*)(sA + i * NX))[jb];
                acc[i] += a.x * x[jb * 4 + 0] + a.y * x[jb * 4 + 1]
                        + a.z * x[jb * 4 + 2] + a.w * x[jb * 4 + 3];
            }
        }
        #pragma unroll
        for (int i = 0; i < NX; i++) x[i] = acc[i];

        up += (size_t)NU * R;
        yp += (size_t)NY * R;
        xp += (size_t)NX * R;
    }
}

// ---------------------------------------------------------------------------
extern "C" void kernel_launch(void* const* d_in, const int* in_sizes, int n_in,
                              void* d_out, int out_size) {
    const float* u  = (const float*)d_in[0];
    const float* x0 = (const float*)d_in[1];
    const float* A  = (const float*)d_in[2];
    const float* B  = (const float*)d_in[3];
    const float* Cy = (const float*)d_in[4];
    const float* D  = (const float*)d_in[5];
    float* outY = (float*)d_out;
    float* outX = (float*)d_out + (size_t)N_STEPS * NY * R;

    k_precompute<<<1, 256>>>(A, B);
    k_phase1<<<dim3(C_CHUNKS, R / 64), 256>>>(u);
    k_phase2<<<R / RSUB, NX * RSUB>>>(x0);
    k_phase3<<<dim3(C_CHUNKS, R / 32), 32>>>(u, A, B, Cy, D, outY, outX);
}

// round 2
// speedup vs baseline: 1.3152x; 1.3152x over previous
#include <cuda_runtime.h>
#include <cstddef>

#define N_STEPS 4096
#define NU 8
#define R 256
#define NX 64
#define NY 8
#define L 32
#define C_CHUNKS (N_STEPS / L)   // 128
#define QTOT (NU * L)            // 256
#define RSUB 2

typedef unsigned long long ull;

// Scratch (device globals: no allocation allowed in kernel_launch)
__device__ float g_KcatT[QTOT * NX];            // [q][i], q=(t*NU+j) with K[L-1-t]
__device__ float g_AL[NX * NX];                 // A^L row-major
__device__ float g_Pfin[C_CHUNKS * NX * R];
__device__ float g_Xstart[C_CHUNKS * NX * R];

// ---------------- packed f32x2 helpers ----------------
__device__ __forceinline__ ull pack2(float lo, float hi) {
    ull v; asm("mov.b64 %0,{%1,%2};" : "=l"(v) : "f"(lo), "f"(hi)); return v;
}
__device__ __forceinline__ void unpack2(ull v, float& lo, float& hi) {
    asm("mov.b64 {%0,%1},%2;" : "=f"(lo), "=f"(hi) : "l"(v));
}
__device__ __forceinline__ ull fma2(ull a, ull b, ull c) {
    ull d; asm("fma.rn.f32x2 %0,%1,%2,%3;" : "=l"(d) : "l"(a), "l"(b), "l"(c)); return d;
}

// ---------------------------------------------------------------------------
// Kernel 0: precompute K[s] = A^s B (time-flipped, transposed) and A^L.
// ---------------------------------------------------------------------------
__global__ void k_precompute(const float* __restrict__ A, const float* __restrict__ B) {
    __shared__ float sP[NX * NX];
    __shared__ float sQ[NX * NX];
    __shared__ float sK0[NX * NU];
    __shared__ float sK1[NX * NU];
    const int t = threadIdx.x;  // 256

    for (int idx = t; idx < NX * NX; idx += 256) sP[idx] = A[idx];
    for (int idx = t; idx < NX * NU; idx += 256) sK0[idx] = B[idx];
    __syncthreads();

    for (int idx = t; idx < NX * NU; idx += 256) {
        int i = idx / NU, j = idx % NU;
        g_KcatT[((L - 1) * NU + j) * NX + i] = sK0[idx];
    }
    float* kc = sK0;
    float* kn = sK1;
    for (int s = 1; s < L; s++) {
        __syncthreads();
        for (int idx = t; idx < NX * NU; idx += 256) {
            int i = idx / NU, j = idx % NU;
            float acc = 0.f;
            #pragma unroll 8
            for (int m = 0; m < NX; m++) acc += sP[i * NX + m] * kc[m * NU + j];
            kn[idx] = acc;
            g_KcatT[((L - 1 - s) * NU + j) * NX + i] = acc;
        }
        float* tmp = kc; kc = kn; kn = tmp;
    }

    float* p = sP;
    float* q = sQ;
    for (int m = 0; m < 5; m++) {
        __syncthreads();
        for (int idx = t; idx < NX * NX; idx += 256) {
            int i = idx / NX, j = idx % NX;
            float a0 = 0.f, a1 = 0.f, a2 = 0.f, a3 = 0.f;
            #pragma unroll 4
            for (int k = 0; k < NX; k += 4) {
                a0 += p[i * NX + k + 0] * p[(k + 0) * NX + j];
                a1 += p[i * NX + k + 1] * p[(k + 1) * NX + j];
                a2 += p[i * NX + k + 2] * p[(k + 2) * NX + j];
                a3 += p[i * NX + k + 3] * p[(k + 3) * NX + j];
            }
            q[idx] = (a0 + a1) + (a2 + a3);
        }
        float* tmp = p; p = q; q = tmp;
    }
    __syncthreads();
    for (int idx = t; idx < NX * NX; idx += 256) g_AL[idx] = p[idx];
}

// ---------------------------------------------------------------------------
// Kernel 1: Pfin[c] = Kcat(64x256) @ Uc(256x256)
// ---------------------------------------------------------------------------
__global__ void k_phase1(const float* __restrict__ u) {
    __shared__ __align__(16) float sU[64 * 64];
    __shared__ __align__(16) float sKT[64 * 64];
    const int c = blockIdx.x;
    const int r0 = blockIdx.y * 64;
    const int t = threadIdx.x;
    const int r = t & 63;
    const int ig = t >> 6;

    float acc[16];
    #pragma unroll
    for (int m = 0; m < 16; m++) acc[m] = 0.f;

    const float* Uc = u + (size_t)c * L * NU * R;

    for (int qb = 0; qb < QTOT / 64; qb++) {
        __syncthreads();
        #pragma unroll
        for (int m = 0; m < 16; m++) {
            int qq = m * 4 + ig;
            sU[qq * 64 + r] = Uc[(size_t)(qb * 64 + qq) * R + r0 + r];
        }
        for (int idx = t; idx < 4096; idx += 256)
            sKT[idx] = g_KcatT[qb * 64 * 64 + idx];
        __syncthreads();

        #pragma unroll 8
        for (int qq = 0; qq < 64; qq++) {
            float uval = sU[qq * 64 + r];
            const float4* k4 = (const float4*)(sKT + qq * 64 + ig * 16);
            #pragma unroll
            for (int m4 = 0; m4 < 4; m4++) {
                float4 kk = k4[m4];
                acc[m4 * 4 + 0] += kk.x * uval;
                acc[m4 * 4 + 1] += kk.y * uval;
                acc[m4 * 4 + 2] += kk.z * uval;
                acc[m4 * 4 + 3] += kk.w * uval;
            }
        }
    }
    #pragma unroll
    for (int m = 0; m < 16; m++) {
        int i = ig * 16 + m;
        g_Pfin[((size_t)c * NX + i) * R + r0 + r] = acc[m];
    }
}

// ---------------------------------------------------------------------------
// Kernel 2: boundary scan with 4-way ILP partial sums.
// ---------------------------------------------------------------------------
__global__ void k_phase2(const float* __restrict__ x0) {
    __shared__ __align__(16) float sAL[NX * NX];
    __shared__ float sx[NX * RSUB];
    const int t = threadIdx.x;  // 128
    const int r = t & (RSUB - 1);
    const int i = t / RSUB;
    const int rg = blockIdx.x * RSUB + r;

    for (int idx = t; idx < NX * NX; idx += NX * RSUB) sAL[idx] = g_AL[idx];
    float xi = x0[i * R + rg];
    sx[i * RSUB + r] = xi;
    __syncthreads();

    float pf = g_Pfin[(size_t)i * R + rg];
    for (int c = 0; c < C_CHUNKS; c++) {
        g_Xstart[((size_t)c * NX + i) * R + rg] = xi;
        float pf_next = (c + 1 < C_CHUNKS)
            ? g_Pfin[((size_t)(c + 1) * NX + i) * R + rg] : 0.f;
        float a0 = 0.f, a1 = 0.f, a2 = 0.f, a3 = 0.f;
        const float4* a4 = (const float4*)(sAL + i * NX);
        #pragma unroll
        for (int jb = 0; jb < NX / 4; jb++) {
            float4 a = a4[jb];
            a0 += a.x * sx[(jb * 4 + 0) * RSUB + r];
            a1 += a.y * sx[(jb * 4 + 1) * RSUB + r];
            a2 += a.z * sx[(jb * 4 + 2) * RSUB + r];
            a3 += a.w * sx[(jb * 4 + 3) * RSUB + r];
        }
        float acc = ((a0 + a1) + (a2 + a3)) + pf;
        __syncthreads();
        xi = acc;
        sx[i * RSUB + r] = xi;
        pf = pf_next;
        __syncthreads();
    }
}

// ---------------------------------------------------------------------------
// Kernel 3 (v2): packed f32x2, half-column per thread.
// Grid (C_CHUNKS, R/64), 128 threads (4 warps). Warp handles 16 columns;
// lane = (half h = lane>>4, col16 = lane&15). Thread owns rows [h*32, h*32+32)
// of one column, kept as 16 packed f32x2 registers.
// ---------------------------------------------------------------------------
__global__ void __launch_bounds__(128) k_phase3(
    const float* __restrict__ u, const float* __restrict__ A,
    const float* __restrict__ B, const float* __restrict__ Cy,
    const float* __restrict__ D,
    float* __restrict__ outY, float* __restrict__ outX)
{
    __shared__ __align__(16) ull sA2[64 * 32];  // [j][i2] = {A[2i2][j], A[2i2+1][j]}
    __shared__ __align__(16) ull sB2[NU * 32];  // [j][i2] = {B[2i2][j], B[2i2+1][j]}
    __shared__ __align__(16) ull sC2[NY * 32];  // [o][j2] = {C[o][2j2], C[o][2j2+1]}
    __shared__ float sD[NY * NU];

    const int tid = threadIdx.x;
    const int warp = tid >> 5;
    const int lane = tid & 31;
    const int col16 = lane & 15;
    const int h = lane >> 4;                 // row half
    const int c = blockIdx.x;                // chunk
    const int r = blockIdx.y * 64 + warp * 16 + col16;

    // Build packed operand matrices in smem
    for (int idx = tid; idx < 64 * 32; idx += 128) {
        int j = idx >> 5, i2 = idx & 31;
        sA2[idx] = pack2(A[(2 * i2) * NX + j], A[(2 * i2 + 1) * NX + j]);
    }
    for (int idx = tid; idx < NU * 32; idx += 128) {
        int j = idx >> 5, i2 = idx & 31;
        sB2[idx] = pack2(B[(2 * i2) * NU + j], B[(2 * i2 + 1) * NU + j]);
    }
    for (int idx = tid; idx < NY * 32; idx += 128) {
        int o = idx >> 5, j2 = idx & 31;
        sC2[idx] = pack2(Cy[o * NX + 2 * j2], Cy[o * NX + 2 * j2 + 1]);
    }
    for (int idx = tid; idx < NY * NU; idx += 128) sD[idx] = D[idx];

    // Load my half of the starting state (rows h*32 .. h*32+31 as 16 pairs)
    ull x2[16];
    {
        const float* xs = g_Xstart + ((size_t)c * NX + h * 32) * R + r;
        #pragma unroll
        for (int k = 0; k < 16; k++)
            x2[k] = pack2(xs[(size_t)(2 * k) * R], xs[(size_t)(2 * k + 1) * R]);
    }
    __syncthreads();

    const float* up  = u    + (size_t)c * L * NU * R + r;
    float*       ypt = outY + (size_t)c * L * NY * R + r;
    float*       xph = outX + ((size_t)c * L * NX + h * 32) * R + r;
    const int hb = h * 16;  // my i2 offset within [0,32)

    #pragma unroll 1
    for (int step = 0; step < L; step++) {
        // ---- inputs ----
        float uu[NU];
        #pragma unroll
        for (int j = 0; j < NU; j++) uu[j] = up[(size_t)j * R];

        // ---- store X[k] (pre-update) ----
        #pragma unroll
        for (int k = 0; k < 16; k++) {
            float lo, hi; unpack2(x2[k], lo, hi);
            xph[(size_t)(2 * k) * R]     = lo;
            xph[(size_t)(2 * k + 1) * R] = hi;
        }

        // ---- Y[k] = C x + D u (half-partials reduced across partner lanes) ----
        {
            float dsum[NY];
            #pragma unroll
            for (int o = 0; o < NY; o++) {
                ull ya = pack2(0.f, 0.f);
                const ulonglong2* c2 = (const ulonglong2*)(sC2 + o * 32 + hb);
                #pragma unroll
                for (int k2 = 0; k2 < 8; k2++) {
                    ulonglong2 cc = c2[k2];
                    ya = fma2(cc.x, x2[2 * k2 + 0], ya);
                    ya = fma2(cc.y, x2[2 * k2 + 1], ya);
                }
                float lo, hi; unpack2(ya, lo, hi);
                float xdot = lo + hi;
                float ds = 0.f;
                #pragma unroll
                for (int j = 0; j < NU; j++) ds += sD[o * NU + j] * uu[j];
                dsum[o] = xdot + __shfl_xor_sync(0xffffffffu, xdot, 16) + ds;
            }
            if (h == 0) {
                #pragma unroll
                for (int o = 0; o < NY; o++) ypt[(size_t)o * R] = dsum[o];
            }
        }

        // ---- acc = B u (packed row pairs) ----
        ull acc2[16];
        {
            ull ur[NU];
            #pragma unroll
            for (int j = 0; j < NU; j++) ur[j] = pack2(uu[j], uu[j]);
            #pragma unroll
            for (int k = 0; k < 16; k += 2) {
                ulonglong2 b0 = *(const ulonglong2*)(sB2 + 0 * 32 + hb + k);
                acc2[k]     = fma2(b0.x, ur[0], pack2(0.f, 0.f));
                acc2[k + 1] = fma2(b0.y, ur[0], pack2(0.f, 0.f));
            }
            #pragma unroll
            for (int j = 1; j < NU; j++) {
                #pragma unroll
                for (int k = 0; k < 16; k += 2) {
                    ulonglong2 bb = *(const ulonglong2*)(sB2 + j * 32 + hb + k);
                    acc2[k]     = fma2(bb.x, ur[j], acc2[k]);
                    acc2[k + 1] = fma2(bb.y, ur[j], acc2[k + 1]);
                }
            }
        }

        // ---- acc += A x (x gathered across the two halves via shuffle) ----
        #pragma unroll
        for (int j2 = 0; j2 < 32; j2++) {
            // pair (x[2*j2], x[2*j2+1]) of the full column lives in lane
            // (col16 | ((j2>>4)<<4)) at local index j2&15
            ull v = __shfl_sync(0xffffffffu, x2[j2 & 15], col16 | (j2 & 16));
            float xa, xb; unpack2(v, xa, xb);
            ull xra = pack2(xa, xa);
            ull xrb = pack2(xb, xb);
            const ulonglong2* a0 = (const ulonglong2*)(sA2 + (2 * j2) * 32 + hb);
            const ulonglong2* a1 = (const ulonglong2*)(sA2 + (2 * j2 + 1) * 32 + hb);
            #pragma unroll
            for (int k2 = 0; k2 < 8; k2++) {
                ulonglong2 aa = a0[k2];
                acc2[2 * k2 + 0] = fma2(aa.x, xra, acc2[2 * k2 + 0]);
                acc2[2 * k2 + 1] = fma2(aa.y, xra, acc2[2 * k2 + 1]);
                ulonglong2 bb = a1[k2];
                acc2[2 * k2 + 0] = fma2(bb.x, xrb, acc2[2 * k2 + 0]);
                acc2[2 * k2 + 1] = fma2(bb.y, xrb, acc2[2 * k2 + 1]);
            }
        }

        #pragma unroll
        for (int k = 0; k < 16; k++) x2[k] = acc2[k];

        up  += (size_t)NU * R;
        ypt += (size_t)NY * R;
        xph += (size_t)NX * R;
    }
}

// ---------------------------------------------------------------------------
extern "C" void kernel_launch(void* const* d_in, const int* in_sizes, int n_in,
                              void* d_out, int out_size) {
    const float* u  = (const float*)d_in[0];
    const float* x0 = (const float*)d_in[1];
    const float* A  = (const float*)d_in[2];
    const float* B  = (const float*)d_in[3];
    const float* Cy = (const float*)d_in[4];
    const float* D  = (const float*)d_in[5];
    float* outY = (float*)d_out;
    float* outX = (float*)d_out + (size_t)N_STEPS * NY * R;

    k_precompute<<<1, 256>>>(A, B);
    k_phase1<<<dim3(C_CHUNKS, R / 64), 256>>>(u);
    k_phase2<<<R / RSUB, NX * RSUB>>>(x0);
    k_phase3<<<dim3(C_CHUNKS, R / 64), 128>>>(u, A, B, Cy, D, outY, outX);
}